// round 3
// baseline (speedup 1.0000x reference)
#include <cuda_runtime.h>
#include <cstdint>
#include <cstddef>

#define B_ 256
#define L_ 512
#define D_ 768
#define C_ 19
#define CP 20
#define BL (B_*L_)

// Emission scratch, padded to 20 floats/row
__device__ float g_emis[(size_t)BL * CP];

__device__ __forceinline__ unsigned long long pack2(float x){
    unsigned long long r;
    asm("mov.b64 %0, {%1, %1};" : "=l"(r) : "f"(x));
    return r;
}
__device__ __forceinline__ unsigned long long fma2(unsigned long long a,
                                                   unsigned long long b,
                                                   unsigned long long c){
    unsigned long long d;
    asm("fma.rn.f32x2 %0, %1, %2, %3;" : "=l"(d) : "l"(a), "l"(b), "l"(c));
    return d;
}

#define SMEM_A (D_ * 10 * 8)   // 61440 bytes: w2[d][p] packed class pairs

// ---------------------------------------------------------------------------
// Kernel A: emissions. 128 blocks x 256 threads, 4 rows/thread, depth-2
// feature prefetch (8 LDG.128 in flight per thread) to cover ~577cyc DRAM lat.
// ---------------------------------------------------------------------------
__global__ void __launch_bounds__(256) emis_kernel(const float* __restrict__ feats,
                                                   const float* __restrict__ W,
                                                   const float* __restrict__ bias){
    extern __shared__ unsigned long long w2[];   // [768*10]
    int tid = threadIdx.x;
    for (int i = tid; i < D_ * 10; i += 256){
        int d = i / 10, p = i % 10;
        float lo = W[(2*p) * D_ + d];
        float hi = (2*p + 1 < C_) ? W[(2*p + 1) * D_ + d] : 0.f;
        float2 t = make_float2(lo, hi);
        w2[i] = *reinterpret_cast<unsigned long long*>(&t);
    }
    __syncthreads();

    unsigned long long acc[4][10];
#pragma unroll
    for (int p = 0; p < 10; p++){
        float lo = bias[2*p];
        float hi = (2*p + 1 < C_) ? bias[2*p + 1] : 0.f;
        float2 t = make_float2(lo, hi);
        unsigned long long bv = *reinterpret_cast<unsigned long long*>(&t);
#pragma unroll
        for (int r = 0; r < 4; r++) acc[r][p] = bv;
    }

    size_t base = (size_t)blockIdx.x * 1024 + tid;
    const float4* f[4];
#pragma unroll
    for (int r = 0; r < 4; r++)
        f[r] = reinterpret_cast<const float4*>(feats + (base + (size_t)r * 256) * D_);

    // depth-2 software pipeline: ring[phase][row]
    float4 ring[2][4];
#pragma unroll
    for (int r = 0; r < 4; r++) ring[0][r] = f[r][0];
#pragma unroll
    for (int r = 0; r < 4; r++) ring[1][r] = f[r][1];

    const int NQ = D_ / 4;   // 192
    for (int q = 0; q < NQ; q++){
        int ph = q & 1;
        float4 c0 = ring[ph][0], c1 = ring[ph][1], c2 = ring[ph][2], c3 = ring[ph][3];
        if (q + 2 < NQ){
#pragma unroll
            for (int r = 0; r < 4; r++) ring[ph][r] = f[r][q + 2];
        }
#pragma unroll
        for (int j = 0; j < 4; j++){
            unsigned long long p0 = pack2((&c0.x)[j]);
            unsigned long long p1 = pack2((&c1.x)[j]);
            unsigned long long p2 = pack2((&c2.x)[j]);
            unsigned long long p3 = pack2((&c3.x)[j]);
            int d = q * 4 + j;
#pragma unroll
            for (int p = 0; p < 10; p++){
                unsigned long long w = w2[d * 10 + p];
                acc[0][p] = fma2(p0, w, acc[0][p]);
                acc[1][p] = fma2(p1, w, acc[1][p]);
                acc[2][p] = fma2(p2, w, acc[2][p]);
                acc[3][p] = fma2(p3, w, acc[3][p]);
            }
        }
    }

#pragma unroll
    for (int r = 0; r < 4; r++){
        unsigned long long* o =
            reinterpret_cast<unsigned long long*>(g_emis + (base + (size_t)r * 256) * CP);
#pragma unroll
        for (int p = 0; p < 10; p++) o[p] = acc[r][p];
    }
}

// ---------------------------------------------------------------------------
// Kernel B: Viterbi. One warp per batch. Score-vector gather via smem
// broadcast: STS own score, 1 syncwarp, 5x LDS.128 (replaces 19 SHFLs).
// Double-buffered staging row -> one syncwarp per step. bp eq-scan issues in
// the latency shadow of the next step's LDS. Masks staged in shared;
// backpointers in shared; coalesced tag writeback.
// ---------------------------------------------------------------------------
__global__ void __launch_bounds__(128) viterbi_kernel(const float* __restrict__ masks,
                                                      const float* __restrict__ trans,
                                                      float* __restrict__ out){
    __shared__ signed char bp_sh[4][L_][CP];      // [..][19] reused for tags
    __shared__ float m_sh[4][L_];
    __shared__ float s_sh[4][2][32];              // double-buffered score vector
    int w = threadIdx.x >> 5, lane = threadIdx.x & 31;
    int b = blockIdx.x * 4 + w;
    bool active = lane < C_;
    int c = active ? lane : 0;

    float Trow[C_];
#pragma unroll
    for (int j = 0; j < C_; j++) Trow[j] = trans[c * C_ + j];
    float tstop = trans[(C_ - 1) * C_ + c];

    const float* eb = g_emis + (size_t)b * L_ * CP;
    const float* mb = masks + (size_t)b * L_;

    for (int i = lane; i < L_; i += 32) m_sh[w][i] = mb[i];

    float s = (lane == C_ - 2) ? 0.f : -10000.f;   // start_idx = C-2

    int ld_lane = active ? lane : 0;
    float e0 = eb[0 * CP + ld_lane];
    float e1 = eb[1 * CP + ld_lane];
    float e2 = eb[2 * CP + ld_lane];
    float e3 = eb[3 * CP + ld_lane];

    // prologue: publish initial scores into buffer 0
    s_sh[w][0][lane] = s;
    __syncwarp();
    float4 g0 = *reinterpret_cast<const float4*>(&s_sh[w][0][0]);
    float4 g1 = *reinterpret_cast<const float4*>(&s_sh[w][0][4]);
    float4 g2 = *reinterpret_cast<const float4*>(&s_sh[w][0][8]);
    float4 g3 = *reinterpret_cast<const float4*>(&s_sh[w][0][12]);
    float4 g4 = *reinterpret_cast<const float4*>(&s_sh[w][0][16]);

#define VSTEP(T, EREG)                                                         \
    {                                                                          \
        float v[C_];                                                           \
        v[0]=g0.x+Trow[0];  v[1]=g0.y+Trow[1];  v[2]=g0.z+Trow[2];             \
        v[3]=g0.w+Trow[3];  v[4]=g1.x+Trow[4];  v[5]=g1.y+Trow[5];             \
        v[6]=g1.z+Trow[6];  v[7]=g1.w+Trow[7];  v[8]=g2.x+Trow[8];             \
        v[9]=g2.y+Trow[9];  v[10]=g2.z+Trow[10]; v[11]=g2.w+Trow[11];          \
        v[12]=g3.x+Trow[12]; v[13]=g3.y+Trow[13]; v[14]=g3.z+Trow[14];         \
        v[15]=g3.w+Trow[15]; v[16]=g4.x+Trow[16]; v[17]=g4.y+Trow[17];         \
        v[18]=g4.z+Trow[18];                                                   \
        float bv[C_];                                                          \
        _Pragma("unroll")                                                      \
        for (int j = 0; j < C_; j++) bv[j] = v[j];                             \
        _Pragma("unroll")                                                      \
        for (int stp = 1; stp < C_; stp <<= 1){                                \
            _Pragma("unroll")                                                  \
            for (int j = 0; j + stp < C_; j += (stp << 1))                     \
                bv[j] = fmaxf(bv[j], bv[j + stp]);                             \
        }                                                                      \
        float mx = bv[0];                                                      \
        float m = m_sh[w][T];                                                  \
        float om = 1.0f - m;                                                   \
        float acc = mx + (EREG);                                               \
        float ns = acc * m;                                                    \
        ns = fmaf(s, om, ns);                                                  \
        s = ns;                                                                \
        /* publish for next step (alternate buffer), then gather */           \
        int nb = (T + 1) & 1;                                                  \
        s_sh[w][nb][lane] = s;                                                 \
        __syncwarp();                                                          \
        g0 = *reinterpret_cast<const float4*>(&s_sh[w][nb][0]);                \
        g1 = *reinterpret_cast<const float4*>(&s_sh[w][nb][4]);                \
        g2 = *reinterpret_cast<const float4*>(&s_sh[w][nb][8]);                \
        g3 = *reinterpret_cast<const float4*>(&s_sh[w][nb][12]);               \
        g4 = *reinterpret_cast<const float4*>(&s_sh[w][nb][16]);               \
        /* bp scan issues under the LDS latency above */                       \
        int bp = C_ - 1;                                                       \
        _Pragma("unroll")                                                      \
        for (int j = C_ - 2; j >= 0; j--) bp = (v[j] == mx) ? j : bp;          \
        if (active) bp_sh[w][T][lane] = (signed char)bp;                       \
    }

    for (int t = 0; t < L_; t += 4){
        VSTEP(t, e0);     e0 = (t + 4 < L_) ? eb[(t + 4) * CP + ld_lane] : 0.f;
        VSTEP(t + 1, e1); e1 = (t + 5 < L_) ? eb[(t + 5) * CP + ld_lane] : 0.f;
        VSTEP(t + 2, e2); e2 = (t + 6 < L_) ? eb[(t + 6) * CP + ld_lane] : 0.f;
        VSTEP(t + 3, e3); e3 = (t + 7 < L_) ? eb[(t + 7) * CP + ld_lane] : 0.f;
    }
#undef VSTEP

    // final = s + transitions[stop]; first-index argmax across lanes
    float fv = active ? (s + tstop) : -3.4e38f;
    int fi = active ? lane : 999;
#pragma unroll
    for (int off = 16; off > 0; off >>= 1){
        float ov = __shfl_down_sync(0xffffffffu, fv, off);
        int oi = __shfl_down_sync(0xffffffffu, fi, off);
        if (ov > fv || (ov == fv && oi < fi)){ fv = ov; fi = oi; }
    }

    if (lane == 0){
        out[b] = fv;
        int cur = fi;
        for (int t = L_ - 1; t >= 0; t--){
            float mt = m_sh[w][t];
            bool valid = mt > 0.f;
            bp_sh[w][t][C_] = valid ? (signed char)cur : (signed char)(-1);
            if (valid) cur = bp_sh[w][t][cur];
        }
    }
    __syncwarp();

    // coalesced tag write
    float* po = out + B_ + (size_t)b * L_;
    for (int i = lane; i < L_; i += 32)
        po[i] = (float)bp_sh[w][i][C_];
}

// ---------------------------------------------------------------------------
extern "C" void kernel_launch(void* const* d_in, const int* in_sizes, int n_in,
                              void* d_out, int out_size){
    const float* feats = (const float*)d_in[0];
    const float* masks = (const float*)d_in[1];
    const float* W     = (const float*)d_in[2];
    const float* bias  = (const float*)d_in[3];
    const float* trans = (const float*)d_in[4];
    float* out = (float*)d_out;

    cudaFuncSetAttribute(emis_kernel, cudaFuncAttributeMaxDynamicSharedMemorySize, SMEM_A);
    emis_kernel<<<128, 256, SMEM_A>>>(feats, W, bias);
    viterbi_kernel<<<B_ / 4, 128>>>(masks, trans, out);
}

// round 4
// speedup vs baseline: 1.0786x; 1.0786x over previous
#include <cuda_runtime.h>
#include <cstdint>
#include <cstddef>

#define B_ 256
#define L_ 512
#define D_ 768
#define C_ 19
#define CP 20
#define BL (B_*L_)

// Emission scratch, padded to 20 floats/row
__device__ float g_emis[(size_t)BL * CP];
// Score history: rows 0..512 per batch (row 0 = init, row t+1 = s after step t)
__device__ float g_hist[(size_t)B_ * (L_ + 1) * CP];

__device__ __forceinline__ unsigned long long pack2(float x){
    unsigned long long r;
    asm("mov.b64 %0, {%1, %1};" : "=l"(r) : "f"(x));
    return r;
}
__device__ __forceinline__ unsigned long long fma2(unsigned long long a,
                                                   unsigned long long b,
                                                   unsigned long long c){
    unsigned long long d;
    asm("fma.rn.f32x2 %0, %1, %2, %3;" : "=l"(d) : "l"(a), "l"(b), "l"(c));
    return d;
}

#define SMEM_A (D_ * 10 * 8)   // 61440 bytes: w2[d][p] packed class pairs

// ---------------------------------------------------------------------------
// Kernel A: emissions (R2 version — known-good perf). 256 blocks x 256
// threads, 2 rows/thread, packed f32x2 FMA, weights broadcast from shared.
// ---------------------------------------------------------------------------
__global__ void __launch_bounds__(256, 2) emis_kernel(const float* __restrict__ feats,
                                                      const float* __restrict__ W,
                                                      const float* __restrict__ bias){
    extern __shared__ unsigned long long w2[];   // [768*10]
    int tid = threadIdx.x;
    for (int i = tid; i < D_ * 10; i += 256){
        int d = i / 10, p = i % 10;
        float lo = W[(2*p) * D_ + d];
        float hi = (2*p + 1 < C_) ? W[(2*p + 1) * D_ + d] : 0.f;
        float2 t = make_float2(lo, hi);
        w2[i] = *reinterpret_cast<unsigned long long*>(&t);
    }
    __syncthreads();

    unsigned long long accA[10], accB[10];
#pragma unroll
    for (int p = 0; p < 10; p++){
        float lo = bias[2*p];
        float hi = (2*p + 1 < C_) ? bias[2*p + 1] : 0.f;
        float2 t = make_float2(lo, hi);
        accA[p] = *reinterpret_cast<unsigned long long*>(&t);
        accB[p] = accA[p];
    }

    size_t rowA = (size_t)blockIdx.x * 512 + tid;
    size_t rowB = rowA + 256;
    const float4* fA = reinterpret_cast<const float4*>(feats + rowA * D_);
    const float4* fB = reinterpret_cast<const float4*>(feats + rowB * D_);

    for (int q = 0; q < D_ / 4; q++){
        float4 a = fA[q], b = fB[q];
#pragma unroll
        for (int j = 0; j < 4; j++){
            float av = (&a.x)[j], bv = (&b.x)[j];
            unsigned long long pa = pack2(av), pb = pack2(bv);
            int d = q * 4 + j;
#pragma unroll
            for (int p = 0; p < 10; p++){
                unsigned long long w = w2[d * 10 + p];
                accA[p] = fma2(pa, w, accA[p]);
                accB[p] = fma2(pb, w, accB[p]);
            }
        }
    }

    unsigned long long* oA = reinterpret_cast<unsigned long long*>(g_emis + rowA * CP);
    unsigned long long* oB = reinterpret_cast<unsigned long long*>(g_emis + rowB * CP);
#pragma unroll
    for (int p = 0; p < 10; p++){ oA[p] = accA[p]; oB[p] = accB[p]; }
}

// ---------------------------------------------------------------------------
// Kernel B1: Viterbi forward only. One warp per batch, 256 blocks. Lean loop:
// no backpointer computation at all — scores streamed to smem (for the gather)
// and to gmem history (for kernel B2).
// ---------------------------------------------------------------------------
__global__ void __launch_bounds__(32) fwd_kernel(const float* __restrict__ masks,
                                                 const float* __restrict__ trans){
    __shared__ float hist_s[L_ + 1][CP];    // 41040 B
    __shared__ float m_sh[L_];              //  2048 B
    int lane = threadIdx.x & 31;
    int b = blockIdx.x;
    bool active = lane < C_;
    int c = active ? lane : 0;

    float Trow[C_];
#pragma unroll
    for (int j = 0; j < C_; j++) Trow[j] = trans[c * C_ + j];

    const float* eb = g_emis + (size_t)b * L_ * CP;
    const float* mb = masks + (size_t)b * L_;
    float* ghb = g_hist + (size_t)b * (L_ + 1) * CP;

    for (int i = lane; i < L_; i += 32) m_sh[i] = mb[i];

    float s = (lane == C_ - 2) ? 0.f : -10000.f;   // start_idx = C-2

    int ld_lane = active ? lane : 0;
    float e0 = eb[0 * CP + ld_lane];
    float e1 = eb[1 * CP + ld_lane];
    float e2 = eb[2 * CP + ld_lane];
    float e3 = eb[3 * CP + ld_lane];

    if (active){ hist_s[0][lane] = s; ghb[lane] = s; }
    if (lane == C_){ hist_s[0][C_] = 0.f; }
    __syncwarp();
    float4 g0 = *reinterpret_cast<const float4*>(&hist_s[0][0]);
    float4 g1 = *reinterpret_cast<const float4*>(&hist_s[0][4]);
    float4 g2 = *reinterpret_cast<const float4*>(&hist_s[0][8]);
    float4 g3 = *reinterpret_cast<const float4*>(&hist_s[0][12]);
    float4 g4 = *reinterpret_cast<const float4*>(&hist_s[0][16]);

#define VSTEP(T, EREG)                                                         \
    {                                                                          \
        float v[C_];                                                           \
        v[0]=g0.x+Trow[0];  v[1]=g0.y+Trow[1];  v[2]=g0.z+Trow[2];             \
        v[3]=g0.w+Trow[3];  v[4]=g1.x+Trow[4];  v[5]=g1.y+Trow[5];             \
        v[6]=g1.z+Trow[6];  v[7]=g1.w+Trow[7];  v[8]=g2.x+Trow[8];             \
        v[9]=g2.y+Trow[9];  v[10]=g2.z+Trow[10]; v[11]=g2.w+Trow[11];          \
        v[12]=g3.x+Trow[12]; v[13]=g3.y+Trow[13]; v[14]=g3.z+Trow[14];         \
        v[15]=g3.w+Trow[15]; v[16]=g4.x+Trow[16]; v[17]=g4.y+Trow[17];         \
        v[18]=g4.z+Trow[18];                                                   \
        _Pragma("unroll")                                                      \
        for (int stp = 1; stp < C_; stp <<= 1){                                \
            _Pragma("unroll")                                                  \
            for (int j = 0; j + stp < C_; j += (stp << 1))                     \
                v[j] = fmaxf(v[j], v[j + stp]);                                \
        }                                                                      \
        float mx = v[0];                                                       \
        float m = m_sh[T];                                                     \
        float om = 1.0f - m;                                                   \
        float acc = mx + (EREG);                                               \
        float ns = acc * m;                                                    \
        ns = fmaf(s, om, ns);                                                  \
        s = ns;                                                                \
        if (active){ hist_s[(T) + 1][lane] = s;                                \
                     ghb[((T) + 1) * CP + lane] = s; }                         \
        __syncwarp();                                                          \
        g0 = *reinterpret_cast<const float4*>(&hist_s[(T)+1][0]);              \
        g1 = *reinterpret_cast<const float4*>(&hist_s[(T)+1][4]);              \
        g2 = *reinterpret_cast<const float4*>(&hist_s[(T)+1][8]);              \
        g3 = *reinterpret_cast<const float4*>(&hist_s[(T)+1][12]);             \
        g4 = *reinterpret_cast<const float4*>(&hist_s[(T)+1][16]);             \
    }

    for (int t = 0; t < L_; t += 4){
        VSTEP(t, e0);     e0 = (t + 4 < L_) ? eb[(t + 4) * CP + ld_lane] : 0.f;
        VSTEP(t + 1, e1); e1 = (t + 5 < L_) ? eb[(t + 5) * CP + ld_lane] : 0.f;
        VSTEP(t + 2, e2); e2 = (t + 6 < L_) ? eb[(t + 6) * CP + ld_lane] : 0.f;
        VSTEP(t + 3, e3); e3 = (t + 7 < L_) ? eb[(t + 7) * CP + ld_lane] : 0.f;
    }
#undef VSTEP
}

// ---------------------------------------------------------------------------
// Kernel B2: backpointers + backtrace. One block per batch, 512 threads =
// one thread per timestep. Each thread recomputes all 19 backpointers for its
// step from the gmem score history (embarrassingly parallel), then thread 0
// backtraces from shared.
// ---------------------------------------------------------------------------
__global__ void __launch_bounds__(512) bp_kernel(const float* __restrict__ masks,
                                                 const float* __restrict__ trans,
                                                 float* __restrict__ out){
    __shared__ float T_sh[C_][CP];
    __shared__ float m2[L_];
    __shared__ signed char bp_sh[L_][CP];   // col 19 reused for tags
    int tid = threadIdx.x;
    int b = blockIdx.x;

    for (int i = tid; i < C_ * CP; i += 512){
        int cc = i / CP, j = i % CP;
        T_sh[cc][j] = (j < C_) ? trans[cc * C_ + j] : 0.f;
    }
    if (tid < L_) m2[tid] = masks[(size_t)b * L_ + tid];
    __syncthreads();

    // per-thread timestep: recompute argmax backpointers
    {
        int t = tid;   // 0..511
        const float* h = g_hist + ((size_t)b * (L_ + 1) + t) * CP;
        float4 h0 = *reinterpret_cast<const float4*>(h + 0);
        float4 h1 = *reinterpret_cast<const float4*>(h + 4);
        float4 h2 = *reinterpret_cast<const float4*>(h + 8);
        float4 h3 = *reinterpret_cast<const float4*>(h + 12);
        float4 h4 = *reinterpret_cast<const float4*>(h + 16);
        float hv[C_];
        hv[0]=h0.x; hv[1]=h0.y; hv[2]=h0.z; hv[3]=h0.w;
        hv[4]=h1.x; hv[5]=h1.y; hv[6]=h1.z; hv[7]=h1.w;
        hv[8]=h2.x; hv[9]=h2.y; hv[10]=h2.z; hv[11]=h2.w;
        hv[12]=h3.x; hv[13]=h3.y; hv[14]=h3.z; hv[15]=h3.w;
        hv[16]=h4.x; hv[17]=h4.y; hv[18]=h4.z;

#pragma unroll
        for (int cc = 0; cc < C_; cc++){
            const float* tr = &T_sh[cc][0];
            float best = hv[0] + tr[0];
            int idx = 0;
#pragma unroll
            for (int j = 1; j < C_; j++){
                float val = hv[j] + tr[j];
                bool gt = val > best;          // strict > : leftmost wins ties
                best = gt ? val : best;
                idx  = gt ? j : idx;
            }
            bp_sh[t][cc] = (signed char)idx;
        }
    }

    // final score + start tag (warp 0)
    float fv = -3.4e38f; int fi = 999;
    if (tid < 32){
        int lane = tid;
        bool active = lane < C_;
        if (active)
            fv = g_hist[((size_t)b * (L_ + 1) + L_) * CP + lane]
               + trans[(C_ - 1) * C_ + lane];
        if (active) fi = lane;
#pragma unroll
        for (int off = 16; off > 0; off >>= 1){
            float ov = __shfl_down_sync(0xffffffffu, fv, off);
            int oi = __shfl_down_sync(0xffffffffu, fi, off);
            if (ov > fv || (ov == fv && oi < fi)){ fv = ov; fi = oi; }
        }
    }
    __syncthreads();

    if (tid == 0){
        out[b] = fv;
        int cur = fi;
        for (int t = L_ - 1; t >= 0; t--){
            bool valid = m2[t] > 0.f;
            bp_sh[t][C_] = valid ? (signed char)cur : (signed char)(-1);
            if (valid) cur = bp_sh[t][cur];
        }
    }
    __syncthreads();

    float* po = out + B_ + (size_t)b * L_;
    po[tid] = (float)bp_sh[tid][C_];
}

// ---------------------------------------------------------------------------
extern "C" void kernel_launch(void* const* d_in, const int* in_sizes, int n_in,
                              void* d_out, int out_size){
    const float* feats = (const float*)d_in[0];
    const float* masks = (const float*)d_in[1];
    const float* W     = (const float*)d_in[2];
    const float* bias  = (const float*)d_in[3];
    const float* trans = (const float*)d_in[4];
    float* out = (float*)d_out;

    cudaFuncSetAttribute(emis_kernel, cudaFuncAttributeMaxDynamicSharedMemorySize, SMEM_A);
    emis_kernel<<<256, 256, SMEM_A>>>(feats, W, bias);
    fwd_kernel<<<B_, 32>>>(masks, trans);
    bp_kernel<<<B_, 512>>>(masks, trans, out);
}

// round 5
// speedup vs baseline: 1.1888x; 1.1022x over previous
#include <cuda_runtime.h>
#include <cstdint>
#include <cstddef>

#define B_ 256
#define L_ 512
#define D_ 768
#define C_ 19
#define CP 20
#define BL (B_*L_)

// Emission scratch, padded to 20 floats/row
__device__ float g_emis[(size_t)BL * CP];
// Score history: rows 0..512 per batch (row 0 = init, row t+1 = s after step t)
__device__ float g_hist[(size_t)B_ * (L_ + 1) * CP];

__device__ __forceinline__ unsigned long long pack2(float x){
    unsigned long long r;
    asm("mov.b64 %0, {%1, %1};" : "=l"(r) : "f"(x));
    return r;
}
__device__ __forceinline__ unsigned long long fma2(unsigned long long a,
                                                   unsigned long long b,
                                                   unsigned long long c){
    unsigned long long d;
    asm("fma.rn.f32x2 %0, %1, %2, %3;" : "=l"(d) : "l"(a), "l"(b), "l"(c));
    return d;
}

#define SMEM_A (D_ * 10 * 8)   // 61440 bytes: w2[d][p] packed class pairs

// ---------------------------------------------------------------------------
// Kernel A: emissions. 128 blocks x 256 threads, 4 rows/thread. Weight loads
// via LDS.128 (2 class-pairs per load): 5 LDS per d instead of 10 -> halves
// L1tex wavefronts (was the 78%-L1 bottleneck). Packed f32x2 FMA.
// ---------------------------------------------------------------------------
__global__ void __launch_bounds__(256) emis_kernel(const float* __restrict__ feats,
                                                   const float* __restrict__ W,
                                                   const float* __restrict__ bias){
    extern __shared__ unsigned long long w2[];   // [768*10]
    int tid = threadIdx.x;
    for (int i = tid; i < D_ * 10; i += 256){
        int d = i / 10, p = i % 10;
        float lo = W[(2*p) * D_ + d];
        float hi = (2*p + 1 < C_) ? W[(2*p + 1) * D_ + d] : 0.f;
        float2 t = make_float2(lo, hi);
        w2[i] = *reinterpret_cast<unsigned long long*>(&t);
    }
    __syncthreads();

    unsigned long long acc[4][10];
#pragma unroll
    for (int p = 0; p < 10; p++){
        float lo = bias[2*p];
        float hi = (2*p + 1 < C_) ? bias[2*p + 1] : 0.f;
        float2 t = make_float2(lo, hi);
        unsigned long long bv = *reinterpret_cast<unsigned long long*>(&t);
#pragma unroll
        for (int r = 0; r < 4; r++) acc[r][p] = bv;
    }

    size_t base = (size_t)blockIdx.x * 1024 + tid;
    const float4* f0 = reinterpret_cast<const float4*>(feats + (base        ) * D_);
    const float4* f1 = reinterpret_cast<const float4*>(feats + (base +  256 ) * D_);
    const float4* f2 = reinterpret_cast<const float4*>(feats + (base +  512 ) * D_);
    const float4* f3 = reinterpret_cast<const float4*>(feats + (base +  768 ) * D_);

    for (int q = 0; q < D_ / 4; q++){
        float4 a = f0[q], b = f1[q], c = f2[q], dd4 = f3[q];
#pragma unroll
        for (int j = 0; j < 4; j++){
            unsigned long long p0 = pack2((&a.x)[j]);
            unsigned long long p1 = pack2((&b.x)[j]);
            unsigned long long p2 = pack2((&c.x)[j]);
            unsigned long long p3 = pack2((&dd4.x)[j]);
            int d = q * 4 + j;
#pragma unroll
            for (int pp = 0; pp < 5; pp++){
                ulonglong2 wv = *reinterpret_cast<const ulonglong2*>(&w2[d * 10 + pp * 2]);
                acc[0][2*pp]   = fma2(p0, wv.x, acc[0][2*pp]);
                acc[0][2*pp+1] = fma2(p0, wv.y, acc[0][2*pp+1]);
                acc[1][2*pp]   = fma2(p1, wv.x, acc[1][2*pp]);
                acc[1][2*pp+1] = fma2(p1, wv.y, acc[1][2*pp+1]);
                acc[2][2*pp]   = fma2(p2, wv.x, acc[2][2*pp]);
                acc[2][2*pp+1] = fma2(p2, wv.y, acc[2][2*pp+1]);
                acc[3][2*pp]   = fma2(p3, wv.x, acc[3][2*pp]);
                acc[3][2*pp+1] = fma2(p3, wv.y, acc[3][2*pp+1]);
            }
        }
    }

#pragma unroll
    for (int r = 0; r < 4; r++){
        unsigned long long* o =
            reinterpret_cast<unsigned long long*>(g_emis + (base + (size_t)r * 256) * CP);
#pragma unroll
        for (int p = 0; p < 10; p++) o[p] = acc[r][p];
    }
}

// ---------------------------------------------------------------------------
// Kernel B1: Viterbi forward, SHFL gather (no smem round trip, no syncwarp on
// the chain). Blend restructured as s' = fma(mx, m, fma(e, m, s*(1-m))) —
// bit-exact for m in {0,1}, and everything except one fma is off the
// critical path. One warp per batch, 256 blocks.
// ---------------------------------------------------------------------------
__global__ void __launch_bounds__(32) fwd_kernel(const float* __restrict__ masks,
                                                 const float* __restrict__ trans){
    __shared__ float m_sh[L_];
    int lane = threadIdx.x & 31;
    int b = blockIdx.x;
    bool active = lane < C_;
    int c = active ? lane : 0;

    float Trow[C_];
#pragma unroll
    for (int j = 0; j < C_; j++) Trow[j] = trans[c * C_ + j];

    const float* eb = g_emis + (size_t)b * L_ * CP;
    const float* mb = masks + (size_t)b * L_;
    float* ghb = g_hist + (size_t)b * (L_ + 1) * CP;

    for (int i = lane; i < L_; i += 32) m_sh[i] = mb[i];
    __syncwarp();

    float s = (lane == C_ - 2) ? 0.f : -10000.f;   // start_idx = C-2
    if (active) ghb[lane] = s;

    int ld_lane = active ? lane : 0;
    float e0 = eb[0 * CP + ld_lane];
    float e1 = eb[1 * CP + ld_lane];
    float e2 = eb[2 * CP + ld_lane];
    float e3 = eb[3 * CP + ld_lane];

#define VSTEP(T, EREG)                                                         \
    {                                                                          \
        float m = m_sh[T];                                                     \
        float om = 1.0f - m;                                                   \
        float inner = fmaf((EREG), m, s * om);   /* off critical path */       \
        float v[C_];                                                           \
        _Pragma("unroll")                                                      \
        for (int j = 0; j < C_; j++)                                           \
            v[j] = __shfl_sync(0xffffffffu, s, j) + Trow[j];                   \
        _Pragma("unroll")                                                      \
        for (int stp = 1; stp < C_; stp <<= 1){                                \
            _Pragma("unroll")                                                  \
            for (int j = 0; j + stp < C_; j += (stp << 1))                     \
                v[j] = fmaxf(v[j], v[j + stp]);                                \
        }                                                                      \
        s = fmaf(v[0], m, inner);                                              \
        if (active) ghb[((T) + 1) * CP + lane] = s;                            \
    }

    for (int t = 0; t < L_; t += 4){
        VSTEP(t, e0);     e0 = (t + 4 < L_) ? eb[(t + 4) * CP + ld_lane] : 0.f;
        VSTEP(t + 1, e1); e1 = (t + 5 < L_) ? eb[(t + 5) * CP + ld_lane] : 0.f;
        VSTEP(t + 2, e2); e2 = (t + 6 < L_) ? eb[(t + 6) * CP + ld_lane] : 0.f;
        VSTEP(t + 3, e3); e3 = (t + 7 < L_) ? eb[(t + 7) * CP + ld_lane] : 0.f;
    }
#undef VSTEP
}

// ---------------------------------------------------------------------------
// Kernel B2: backpointers + backtrace. One block per batch, one thread per
// timestep recomputes all 19 backpointers from the score history; thread 0
// backtraces from shared; coalesced tag writeback.
// ---------------------------------------------------------------------------
__global__ void __launch_bounds__(512) bp_kernel(const float* __restrict__ masks,
                                                 const float* __restrict__ trans,
                                                 float* __restrict__ out){
    __shared__ float T_sh[C_][CP];
    __shared__ float m2[L_];
    __shared__ signed char bp_sh[L_][CP];   // col 19 reused for tags
    int tid = threadIdx.x;
    int b = blockIdx.x;

    for (int i = tid; i < C_ * CP; i += 512){
        int cc = i / CP, j = i % CP;
        T_sh[cc][j] = (j < C_) ? trans[cc * C_ + j] : 0.f;
    }
    if (tid < L_) m2[tid] = masks[(size_t)b * L_ + tid];
    __syncthreads();

    {
        int t = tid;   // 0..511
        const float* h = g_hist + ((size_t)b * (L_ + 1) + t) * CP;
        float4 h0 = *reinterpret_cast<const float4*>(h + 0);
        float4 h1 = *reinterpret_cast<const float4*>(h + 4);
        float4 h2 = *reinterpret_cast<const float4*>(h + 8);
        float4 h3 = *reinterpret_cast<const float4*>(h + 12);
        float4 h4 = *reinterpret_cast<const float4*>(h + 16);
        float hv[C_];
        hv[0]=h0.x; hv[1]=h0.y; hv[2]=h0.z; hv[3]=h0.w;
        hv[4]=h1.x; hv[5]=h1.y; hv[6]=h1.z; hv[7]=h1.w;
        hv[8]=h2.x; hv[9]=h2.y; hv[10]=h2.z; hv[11]=h2.w;
        hv[12]=h3.x; hv[13]=h3.y; hv[14]=h3.z; hv[15]=h3.w;
        hv[16]=h4.x; hv[17]=h4.y; hv[18]=h4.z;

#pragma unroll
        for (int cc = 0; cc < C_; cc++){
            const float* tr = &T_sh[cc][0];
            float best = hv[0] + tr[0];
            int idx = 0;
#pragma unroll
            for (int j = 1; j < C_; j++){
                float val = hv[j] + tr[j];
                bool gt = val > best;          // strict > : leftmost wins ties
                best = gt ? val : best;
                idx  = gt ? j : idx;
            }
            bp_sh[t][cc] = (signed char)idx;
        }
    }

    // final score + start tag (warp 0)
    float fv = -3.4e38f; int fi = 999;
    if (tid < 32){
        int lane = tid;
        bool active = lane < C_;
        if (active)
            fv = g_hist[((size_t)b * (L_ + 1) + L_) * CP + lane]
               + trans[(C_ - 1) * C_ + lane];
        if (active) fi = lane;
#pragma unroll
        for (int off = 16; off > 0; off >>= 1){
            float ov = __shfl_down_sync(0xffffffffu, fv, off);
            int oi = __shfl_down_sync(0xffffffffu, fi, off);
            if (ov > fv || (ov == fv && oi < fi)){ fv = ov; fi = oi; }
        }
    }
    __syncthreads();

    if (tid == 0){
        out[b] = fv;
        int cur = fi;
        for (int t = L_ - 1; t >= 0; t--){
            bool valid = m2[t] > 0.f;
            bp_sh[t][C_] = valid ? (signed char)cur : (signed char)(-1);
            if (valid) cur = bp_sh[t][cur];
        }
    }
    __syncthreads();

    float* po = out + B_ + (size_t)b * L_;
    po[tid] = (float)bp_sh[tid][C_];
}

// ---------------------------------------------------------------------------
extern "C" void kernel_launch(void* const* d_in, const int* in_sizes, int n_in,
                              void* d_out, int out_size){
    const float* feats = (const float*)d_in[0];
    const float* masks = (const float*)d_in[1];
    const float* W     = (const float*)d_in[2];
    const float* bias  = (const float*)d_in[3];
    const float* trans = (const float*)d_in[4];
    float* out = (float*)d_out;

    cudaFuncSetAttribute(emis_kernel, cudaFuncAttributeMaxDynamicSharedMemorySize, SMEM_A);
    emis_kernel<<<128, 256, SMEM_A>>>(feats, W, bias);
    fwd_kernel<<<B_, 32>>>(masks, trans);
    bp_kernel<<<B_, 512>>>(masks, trans, out);
}